// round 16
// baseline (speedup 1.0000x reference)
#include <cuda_runtime.h>
#include <cuda_fp16.h>
#include <cstdint>

// ---------------- problem constants ----------------
#define T_TOK   8192
#define D_DIM   1024
#define FF_DIM  4096
#define E_NUM   16
#define K_TOP   2
#define EPS     1e-6f

#define BM 128
#define BN 128
#define BK 32
#define NSTAGE 3
#define ROWS_MAX 18432

#define AS_STRIDE 40           // halves per A row (80B)
#define BS_STRIDE 136          // halves per B k-row (272B)
#define AS_STAGE  (BM * AS_STRIDE)
#define BS_STAGE  (BK * BS_STRIDE)
#define SMEM_DYN  (NSTAGE * (AS_STAGE + BS_STAGE) * 2)   // 56832 bytes

// ---------------- scratch ----------------
__device__ float  g_xn [(size_t)T_TOK * D_DIM];                 // fp32 for gate
__device__ __half g_xnr[(size_t)T_TOK * D_DIM];                 // fp16 for GEMM1
__device__ __half g_h  [(size_t)ROWS_MAX * FF_DIM];
__device__ float  g_y  [(size_t)ROWS_MAX * D_DIM];
__device__ __half g_wih[(size_t)E_NUM * D_DIM * FF_DIM];        // rn(wi) k-major
__device__ __half g_woh[(size_t)E_NUM * FF_DIM * D_DIM];        // rn(wo) k-major
__device__ int    g_cnt [E_NUM];
__device__ int    g_cnt2[E_NUM];
__device__ int    g_off [E_NUM + 1];
__device__ int    g_row_token[ROWS_MAX];
__device__ float  g_row_scale[ROWS_MAX];
__device__ int    g_tok_row[T_TOK * K_TOP];
__device__ int    g_tok_e  [T_TOK * K_TOP];
__device__ float  g_tok_s  [T_TOK * K_TOP];

// ---------------- helpers ----------------
__device__ __forceinline__ void mma_f16(float* c, const unsigned* a, const unsigned* b) {
    asm volatile(
        "mma.sync.aligned.m16n8k16.row.col.f32.f16.f16.f32 "
        "{%0,%1,%2,%3}, {%4,%5,%6,%7}, {%8,%9}, {%0,%1,%2,%3};"
        : "+f"(c[0]), "+f"(c[1]), "+f"(c[2]), "+f"(c[3])
        : "r"(a[0]), "r"(a[1]), "r"(a[2]), "r"(a[3]), "r"(b[0]), "r"(b[1]));
}
__device__ __forceinline__ void ldsm_x4(unsigned* r, uint32_t saddr) {
    asm volatile("ldmatrix.sync.aligned.m8n8.x4.shared.b16 {%0,%1,%2,%3}, [%4];"
                 : "=r"(r[0]), "=r"(r[1]), "=r"(r[2]), "=r"(r[3]) : "r"(saddr));
}
__device__ __forceinline__ void ldsm_x4_trans(unsigned* r, uint32_t saddr) {
    asm volatile("ldmatrix.sync.aligned.m8n8.x4.trans.shared.b16 {%0,%1,%2,%3}, [%4];"
                 : "=r"(r[0]), "=r"(r[1]), "=r"(r[2]), "=r"(r[3]) : "r"(saddr));
}
__device__ __forceinline__ void cp16(void* smem, const void* g) {
    unsigned s = (unsigned)__cvta_generic_to_shared(smem);
    asm volatile("cp.async.cg.shared.global [%0], [%1], 16;" :: "r"(s), "l"(g));
}
__device__ __forceinline__ void cp_commit() { asm volatile("cp.async.commit_group;" ::: "memory"); }
__device__ __forceinline__ uint32_t su32(const void* p) {
    return (uint32_t)__cvta_generic_to_shared(p);
}

// ---------------- streaming fp32 -> fp16 weight convert ----------------
__global__ __launch_bounds__(256) void convert_kernel(const float* __restrict__ src,
                                                      __half* __restrict__ dst) {
    size_t i = (size_t)blockIdx.x * blockDim.x + threadIdx.x;
    float4 v = ((const float4*)src)[i];
    __half2 h0 = __floats2half2_rn(v.x, v.y);
    __half2 h1 = __floats2half2_rn(v.z, v.w);
    uint2 pk;
    pk.x = *(unsigned*)&h0;
    pk.y = *(unsigned*)&h1;
    ((uint2*)dst)[i] = pk;
}

// ---------------- RMSNorm (+ scratch reset folded in) ----------------
__global__ __launch_bounds__(256) void rmsnorm_kernel(const float* __restrict__ x,
                                                      const float* __restrict__ w) {
    int t = blockIdx.x;
    int tid = threadIdx.x;

    int ri = t * 256 + tid;
    if (ri < ROWS_MAX) g_row_token[ri] = -1;
    if (t == 0 && tid < E_NUM) { g_cnt[tid] = 0; g_cnt2[tid] = 0; }

    const float4* xr = (const float4*)(x + (size_t)t * D_DIM);
    float4 v = xr[tid];
    float ss = v.x * v.x + v.y * v.y + v.z * v.z + v.w * v.w;

    __shared__ float red[256];
    red[tid] = ss;
    __syncthreads();
    for (int s = 128; s > 0; s >>= 1) {
        if (tid < s) red[tid] += red[tid + s];
        __syncthreads();
    }
    float inv = rsqrtf(red[0] * (1.0f / (float)D_DIM) + EPS);

    float4 wv = ((const float4*)w)[tid];
    float4 o;
    o.x = v.x * inv * wv.x;
    o.y = v.y * inv * wv.y;
    o.z = v.z * inv * wv.z;
    o.w = v.w * inv * wv.w;
    ((float4*)(g_xn + (size_t)t * D_DIM))[tid] = o;
    __half2* hr = (__half2*)(g_xnr + (size_t)t * D_DIM);
    hr[tid * 2 + 0] = __floats2half2_rn(o.x, o.y);
    hr[tid * 2 + 1] = __floats2half2_rn(o.z, o.w);
}

// ---------------- gate: 4 tokens per warp, gw loads amortized 4x ----------------
__global__ __launch_bounds__(256) void gate_kernel(const float* __restrict__ gw,
                                                   const float* __restrict__ gb) {
    int warp = threadIdx.x >> 5, lane = threadIdx.x & 31;
    int t0 = blockIdx.x * 32 + warp * 4;

    float acc[4][E_NUM];
#pragma unroll
    for (int j = 0; j < 4; j++)
#pragma unroll
        for (int e = 0; e < E_NUM; e++) acc[j][e] = 0.0f;

    for (int d = lane; d < D_DIM; d += 32) {
        const float4* wr = (const float4*)(gw + (size_t)d * E_NUM);
        float4 w0 = wr[0], w1 = wr[1], w2 = wr[2], w3 = wr[3];
#pragma unroll
        for (int j = 0; j < 4; j++) {
            float xv = g_xn[(size_t)(t0 + j) * D_DIM + d];
            acc[j][0]  += xv * w0.x; acc[j][1]  += xv * w0.y;
            acc[j][2]  += xv * w0.z; acc[j][3]  += xv * w0.w;
            acc[j][4]  += xv * w1.x; acc[j][5]  += xv * w1.y;
            acc[j][6]  += xv * w1.z; acc[j][7]  += xv * w1.w;
            acc[j][8]  += xv * w2.x; acc[j][9]  += xv * w2.y;
            acc[j][10] += xv * w2.z; acc[j][11] += xv * w2.w;
            acc[j][12] += xv * w3.x; acc[j][13] += xv * w3.y;
            acc[j][14] += xv * w3.z; acc[j][15] += xv * w3.w;
        }
    }
#pragma unroll
    for (int j = 0; j < 4; j++)
#pragma unroll
        for (int e = 0; e < E_NUM; e++) {
#pragma unroll
            for (int o = 16; o > 0; o >>= 1)
                acc[j][e] += __shfl_down_sync(0xFFFFFFFFu, acc[j][e], o);
        }

    if (lane == 0) {
#pragma unroll
        for (int j = 0; j < 4; j++) {
            int t = t0 + j;
            float v0 = -1e30f, v1 = -1e30f;
            int e0 = 0, e1 = 0;
#pragma unroll
            for (int e = 0; e < E_NUM; e++) {
                float val = acc[j][e] + gb[e];
                if (val > v0) { v1 = v0; e1 = e0; v0 = val; e0 = e; }
                else if (val > v1) { v1 = val; e1 = e; }
            }
            float ex = expf(v1 - v0);
            float s0 = 1.0f / (1.0f + ex);
            float s1 = ex * s0;
            g_tok_e[2 * t + 0] = e0; g_tok_s[2 * t + 0] = s0;
            g_tok_e[2 * t + 1] = e1; g_tok_s[2 * t + 1] = s1;
            atomicAdd(&g_cnt[e0], 1);
            atomicAdd(&g_cnt[e1], 1);
        }
    }
}

// ---------------- offsets ----------------
__global__ void offsets_kernel() {
    if (threadIdx.x == 0 && blockIdx.x == 0) {
        int o = 0;
        for (int e = 0; e < E_NUM; e++) {
            g_off[e] = o;
            o += ((g_cnt[e] + BM - 1) / BM) * BM;
        }
        g_off[E_NUM] = o;
    }
}

// ---------------- scatter ----------------
__global__ __launch_bounds__(256) void scatter_kernel() {
    int t = blockIdx.x * blockDim.x + threadIdx.x;
    if (t >= T_TOK) return;
#pragma unroll
    for (int k = 0; k < K_TOP; k++) {
        int e = g_tok_e[2 * t + k];
        int r = g_off[e] + atomicAdd(&g_cnt2[e], 1);
        g_row_token[r] = t;
        g_row_scale[r] = g_tok_s[2 * t + k];
        g_tok_row[2 * t + k] = r;
    }
}

// =========================================================================
// Grouped FP16 GEMMs (fp32 accumulate), 3-stage cp.async, B k-major in SMEM
// with ldmatrix.trans fragments. 128 threads = 4 warps (2x2), warp 64x64.
// 3 CTAs/SM to fill barrier/tail bubbles.
// =========================================================================
template<int MODE>
__global__ __launch_bounds__(128, 3) void moe_gemm_kernel() {
    constexpr int KT   = (MODE == 0) ? D_DIM : FF_DIM;
    constexpr int NTOT = (MODE == 0) ? FF_DIM : D_DIM;
    constexpr int T    = KT / BK;

    int r0 = blockIdx.y * BM;
    int n0 = blockIdx.x * BN;
    if (g_row_token[r0] < 0) return;

    int e = 0;
    while (r0 >= g_off[e + 1]) e++;
    const __half* Bg = ((MODE == 0) ? g_wih : g_woh) + (size_t)e * D_DIM * FF_DIM;

    extern __shared__ __half smh[];
    __half* As = smh;
    __half* Bs = smh + NSTAGE * AS_STAGE;

    __shared__ int s_tok[BM];

    int tid  = threadIdx.x;
    int wid  = tid >> 5, lane = tid & 31;
    int wm   = wid & 1,  wn   = wid >> 1;
    int gid  = lane >> 2, tg  = lane & 3;

    if (MODE == 0) {
        int tk = g_row_token[r0 + tid];
        s_tok[tid] = tk < 0 ? 0 : tk;
    }
    __syncthreads();

    uint32_t aoff[4], boff[4];
    {
        int l = lane;
        int arow_in = l & 15;
        int akbyte  = (l >> 4) * 16;
#pragma unroll
        for (int mt = 0; mt < 4; mt++)
            aoff[mt] = (uint32_t)((wm * 64 + mt * 16 + arow_in) * AS_STRIDE * 2 + akbyte);
        int i4 = l >> 3, j = l & 7;
        int krow = (i4 & 1) * 8 + j;
        int nadd = (i4 >> 1) * 8;
#pragma unroll
        for (int q = 0; q < 4; q++)
            boff[q] = (uint32_t)((krow * BS_STRIDE + wn * 64 + q * 16 + nadd) * 2);
    }
    uint32_t aBase = su32(As), bBase = su32(Bs);

    auto load_stage = [&](int kt, int s) {
        int k0 = kt * BK;
#pragma unroll
        for (int j = 0; j < 4; j++) {
            int c = tid + 128 * j;
            int row = c >> 2;
            int seg = (c & 3) * 8;
            const __half* src;
            if (MODE == 0) src = g_xnr + (size_t)s_tok[row] * D_DIM + k0 + seg;
            else           src = g_h   + (size_t)(r0 + row) * FF_DIM + k0 + seg;
            cp16(&As[s * AS_STAGE + row * AS_STRIDE + seg], src);
        }
#pragma unroll
        for (int j = 0; j < 4; j++) {
            int c = tid + 128 * j;
            int row = c >> 4;
            int seg = (c & 15) * 8;
            const __half* src = Bg + (size_t)(k0 + row) * NTOT + n0 + seg;
            cp16(&Bs[s * BS_STAGE + row * BS_STRIDE + seg], src);
        }
        cp_commit();
    };

    float c[4][8][4];
#pragma unroll
    for (int mt = 0; mt < 4; mt++)
#pragma unroll
        for (int nt = 0; nt < 8; nt++)
#pragma unroll
            for (int i = 0; i < 4; i++) c[mt][nt][i] = 0.0f;

    load_stage(0, 0);
    load_stage(1, 1);

    int s = 0;
    for (int i = 0; i < T; i++) {
        if (i + 2 < T) asm volatile("cp.async.wait_group 1;" ::: "memory");
        else           asm volatile("cp.async.wait_group 0;" ::: "memory");
        __syncthreads();

        if (i + 2 < T) load_stage(i + 2, (s + 2) % NSTAGE);

        uint32_t stA = aBase + (uint32_t)(s * AS_STAGE * 2);
        uint32_t stB = bBase + (uint32_t)(s * BS_STAGE * 2);
#pragma unroll
        for (int kk = 0; kk < BK; kk += 16) {
            unsigned a[4][4], b[4][4];
#pragma unroll
            for (int mt = 0; mt < 4; mt++)
                ldsm_x4(a[mt], stA + aoff[mt] + kk * 2);
#pragma unroll
            for (int q = 0; q < 4; q++)
                ldsm_x4_trans(b[q], stB + boff[q] + kk * BS_STRIDE * 2);
#pragma unroll
            for (int mt = 0; mt < 4; mt++)
#pragma unroll
                for (int q = 0; q < 4; q++) {
                    mma_f16(c[mt][2 * q + 0], a[mt], &b[q][0]);
                    mma_f16(c[mt][2 * q + 1], a[mt], &b[q][2]);
                }
        }
        s = (s + 1) % NSTAGE;
    }

#pragma unroll
    for (int mt = 0; mt < 4; mt++) {
        int rA = r0 + wm * 64 + mt * 16 + gid;
        if (MODE == 0) {
#pragma unroll
            for (int nt = 0; nt < 8; nt++) {
                int col = n0 + wn * 64 + (nt >> 1) * 16 + (nt & 1) * 8 + tg * 2;
                *(__half2*)&g_h[(size_t)rA * FF_DIM + col] =
                    __floats2half2_rn(fmaxf(c[mt][nt][0], 0.f), fmaxf(c[mt][nt][1], 0.f));
                *(__half2*)&g_h[(size_t)(rA + 8) * FF_DIM + col] =
                    __floats2half2_rn(fmaxf(c[mt][nt][2], 0.f), fmaxf(c[mt][nt][3], 0.f));
            }
        } else {
            float s0 = g_row_scale[rA];
            float s1 = g_row_scale[rA + 8];
#pragma unroll
            for (int nt = 0; nt < 8; nt++) {
                int col = n0 + wn * 64 + (nt >> 1) * 16 + (nt & 1) * 8 + tg * 2;
                float2 lo, hi;
                lo.x = s0 * c[mt][nt][0]; lo.y = s0 * c[mt][nt][1];
                hi.x = s1 * c[mt][nt][2]; hi.y = s1 * c[mt][nt][3];
                *(float2*)&g_y[(size_t)rA       * D_DIM + col] = lo;
                *(float2*)&g_y[(size_t)(rA + 8) * D_DIM + col] = hi;
            }
        }
    }
}

// ---------------- combine ----------------
__global__ __launch_bounds__(256) void combine_kernel(const float* __restrict__ hidden,
                                                      float* __restrict__ out) {
    int i = blockIdx.x * blockDim.x + threadIdx.x;
    int t = i >> 8;
    int d4 = i & 255;
    int r0 = g_tok_row[2 * t + 0];
    int r1 = g_tok_row[2 * t + 1];
    float4 h  = ((const float4*)hidden)[i];
    float4 y0 = ((const float4*)(g_y + (size_t)r0 * D_DIM))[d4];
    float4 y1 = ((const float4*)(g_y + (size_t)r1 * D_DIM))[d4];
    float4 o;
    o.x = h.x + y0.x + y1.x;
    o.y = h.y + y0.y + y1.y;
    o.z = h.z + y0.z + y1.z;
    o.w = h.w + y0.w + y1.w;
    ((float4*)out)[i] = o;
}

// ---------------- launch ----------------
extern "C" void kernel_launch(void* const* d_in, const int* in_sizes, int n_in,
                              void* d_out, int out_size) {
    const float* hidden = (const float*)d_in[0];
    const float* ln_w   = (const float*)d_in[1];
    const float* gate_w = (const float*)d_in[2];
    const float* gate_b = (const float*)d_in[3];
    const float* wi     = (const float*)d_in[4];
    const float* wo     = (const float*)d_in[5];
    float* out = (float*)d_out;

    static cudaStream_t s2 = nullptr;
    static cudaEvent_t evFork = nullptr, evWi = nullptr, evWo = nullptr;
    static int configured = 0;
    if (!configured) {
        cudaFuncSetAttribute(moe_gemm_kernel<0>, cudaFuncAttributeMaxDynamicSharedMemorySize, SMEM_DYN);
        cudaFuncSetAttribute(moe_gemm_kernel<1>, cudaFuncAttributeMaxDynamicSharedMemorySize, SMEM_DYN);
        cudaStreamCreateWithFlags(&s2, cudaStreamNonBlocking);
        cudaEventCreateWithFlags(&evFork, cudaEventDisableTiming);
        cudaEventCreateWithFlags(&evWi, cudaEventDisableTiming);
        cudaEventCreateWithFlags(&evWo, cudaEventDisableTiming);
        configured = 1;
    }

    __half* wih; cudaGetSymbolAddress((void**)&wih, g_wih);
    __half* woh; cudaGetSymbolAddress((void**)&woh, g_woh);
    const unsigned WBLK = (unsigned)((size_t)E_NUM * D_DIM * FF_DIM / 4 / 256);

    // fork: converts on s2; wi first (GEMM1 dep), wo overlaps GEMM1
    cudaEventRecord(evFork, 0);
    cudaStreamWaitEvent(s2, evFork, 0);
    convert_kernel<<<WBLK, 256, 0, s2>>>(wi, wih);
    cudaEventRecord(evWi, s2);
    convert_kernel<<<WBLK, 256, 0, s2>>>(wo, woh);
    cudaEventRecord(evWo, s2);

    // token path
    rmsnorm_kernel<<<T_TOK, 256>>>(hidden, ln_w);          // resets scratch
    gate_kernel<<<T_TOK / 32, 256>>>(gate_w, gate_b);
    offsets_kernel<<<1, 32>>>();
    scatter_kernel<<<(T_TOK + 255) / 256, 256>>>();

    cudaStreamWaitEvent(0, evWi, 0);
    moe_gemm_kernel<0><<<dim3(FF_DIM / BN, ROWS_MAX / BM), 128, SMEM_DYN>>>();
    cudaStreamWaitEvent(0, evWo, 0);
    moe_gemm_kernel<1><<<dim3(D_DIM / BN, ROWS_MAX / BM), 128, SMEM_DYN>>>();
    combine_kernel<<<(T_TOK * D_DIM / 4) / 256, 256>>>(hidden, out);
}

// round 17
// speedup vs baseline: 1.1108x; 1.1108x over previous
#include <cuda_runtime.h>
#include <cuda_fp16.h>
#include <cstdint>

// ---------------- problem constants ----------------
#define T_TOK   8192
#define D_DIM   1024
#define FF_DIM  4096
#define E_NUM   16
#define K_TOP   2
#define EPS     1e-6f

#define BM 128
#define BN 128
#define BK 32
#define NSTAGE 4
#define ROWS_MAX 18432

#define AS_STRIDE 40           // halves per A row (80B)
#define BS_STRIDE 136          // halves per B k-row (272B)
#define AS_STAGE  (BM * AS_STRIDE)
#define BS_STAGE  (BK * BS_STRIDE)
#define SMEM_DYN  (NSTAGE * (AS_STAGE + BS_STAGE) * 2)   // 75776 bytes

// ---------------- scratch ----------------
__device__ float  g_xn [(size_t)T_TOK * D_DIM];                 // fp32 for gate
__device__ __half g_xnr[(size_t)T_TOK * D_DIM];                 // fp16 for GEMM1
__device__ __half g_h  [(size_t)ROWS_MAX * FF_DIM];
__device__ float  g_y  [(size_t)ROWS_MAX * D_DIM];
__device__ __half g_wih[(size_t)E_NUM * D_DIM * FF_DIM];        // rn(wi) k-major
__device__ __half g_woh[(size_t)E_NUM * FF_DIM * D_DIM];        // rn(wo) k-major
__device__ int    g_cnt [E_NUM];
__device__ int    g_cnt2[E_NUM];
__device__ int    g_off [E_NUM + 1];
__device__ int    g_row_token[ROWS_MAX];
__device__ float  g_row_scale[ROWS_MAX];
__device__ int    g_tok_row[T_TOK * K_TOP];
__device__ int    g_tok_e  [T_TOK * K_TOP];
__device__ float  g_tok_s  [T_TOK * K_TOP];

// ---------------- helpers ----------------
__device__ __forceinline__ void mma_f16(float* c, const unsigned* a, const unsigned* b) {
    asm volatile(
        "mma.sync.aligned.m16n8k16.row.col.f32.f16.f16.f32 "
        "{%0,%1,%2,%3}, {%4,%5,%6,%7}, {%8,%9}, {%0,%1,%2,%3};"
        : "+f"(c[0]), "+f"(c[1]), "+f"(c[2]), "+f"(c[3])
        : "r"(a[0]), "r"(a[1]), "r"(a[2]), "r"(a[3]), "r"(b[0]), "r"(b[1]));
}
__device__ __forceinline__ void ldsm_x4(unsigned* r, uint32_t saddr) {
    asm volatile("ldmatrix.sync.aligned.m8n8.x4.shared.b16 {%0,%1,%2,%3}, [%4];"
                 : "=r"(r[0]), "=r"(r[1]), "=r"(r[2]), "=r"(r[3]) : "r"(saddr));
}
__device__ __forceinline__ void ldsm_x4_trans(unsigned* r, uint32_t saddr) {
    asm volatile("ldmatrix.sync.aligned.m8n8.x4.trans.shared.b16 {%0,%1,%2,%3}, [%4];"
                 : "=r"(r[0]), "=r"(r[1]), "=r"(r[2]), "=r"(r[3]) : "r"(saddr));
}
__device__ __forceinline__ void cp16(void* smem, const void* g) {
    unsigned s = (unsigned)__cvta_generic_to_shared(smem);
    asm volatile("cp.async.cg.shared.global [%0], [%1], 16;" :: "r"(s), "l"(g));
}
__device__ __forceinline__ void cp_commit() { asm volatile("cp.async.commit_group;" ::: "memory"); }
__device__ __forceinline__ uint32_t su32(const void* p) {
    return (uint32_t)__cvta_generic_to_shared(p);
}

// ---------------- streaming fp32 -> fp16 weight convert ----------------
__global__ __launch_bounds__(256) void convert_kernel(const float* __restrict__ src,
                                                      __half* __restrict__ dst) {
    size_t i = (size_t)blockIdx.x * blockDim.x + threadIdx.x;
    float4 v = ((const float4*)src)[i];
    __half2 h0 = __floats2half2_rn(v.x, v.y);
    __half2 h1 = __floats2half2_rn(v.z, v.w);
    uint2 pk;
    pk.x = *(unsigned*)&h0;
    pk.y = *(unsigned*)&h1;
    ((uint2*)dst)[i] = pk;
}

// ---------------- RMSNorm (+ scratch reset folded in) ----------------
__global__ __launch_bounds__(256) void rmsnorm_kernel(const float* __restrict__ x,
                                                      const float* __restrict__ w) {
    int t = blockIdx.x;
    int tid = threadIdx.x;

    int ri = t * 256 + tid;
    if (ri < ROWS_MAX) g_row_token[ri] = -1;
    if (t == 0 && tid < E_NUM) { g_cnt[tid] = 0; g_cnt2[tid] = 0; }

    const float4* xr = (const float4*)(x + (size_t)t * D_DIM);
    float4 v = xr[tid];
    float ss = v.x * v.x + v.y * v.y + v.z * v.z + v.w * v.w;

    __shared__ float red[256];
    red[tid] = ss;
    __syncthreads();
    for (int s = 128; s > 0; s >>= 1) {
        if (tid < s) red[tid] += red[tid + s];
        __syncthreads();
    }
    float inv = rsqrtf(red[0] * (1.0f / (float)D_DIM) + EPS);

    float4 wv = ((const float4*)w)[tid];
    float4 o;
    o.x = v.x * inv * wv.x;
    o.y = v.y * inv * wv.y;
    o.z = v.z * inv * wv.z;
    o.w = v.w * inv * wv.w;
    ((float4*)(g_xn + (size_t)t * D_DIM))[tid] = o;
    __half2* hr = (__half2*)(g_xnr + (size_t)t * D_DIM);
    hr[tid * 2 + 0] = __floats2half2_rn(o.x, o.y);
    hr[tid * 2 + 1] = __floats2half2_rn(o.z, o.w);
}

// ---------------- gate: 4 tokens per warp, gw loads amortized 4x ----------------
__global__ __launch_bounds__(256) void gate_kernel(const float* __restrict__ gw,
                                                   const float* __restrict__ gb) {
    int warp = threadIdx.x >> 5, lane = threadIdx.x & 31;
    int t0 = blockIdx.x * 32 + warp * 4;

    float acc[4][E_NUM];
#pragma unroll
    for (int j = 0; j < 4; j++)
#pragma unroll
        for (int e = 0; e < E_NUM; e++) acc[j][e] = 0.0f;

    for (int d = lane; d < D_DIM; d += 32) {
        const float4* wr = (const float4*)(gw + (size_t)d * E_NUM);
        float4 w0 = wr[0], w1 = wr[1], w2 = wr[2], w3 = wr[3];
#pragma unroll
        for (int j = 0; j < 4; j++) {
            float xv = g_xn[(size_t)(t0 + j) * D_DIM + d];
            acc[j][0]  += xv * w0.x; acc[j][1]  += xv * w0.y;
            acc[j][2]  += xv * w0.z; acc[j][3]  += xv * w0.w;
            acc[j][4]  += xv * w1.x; acc[j][5]  += xv * w1.y;
            acc[j][6]  += xv * w1.z; acc[j][7]  += xv * w1.w;
            acc[j][8]  += xv * w2.x; acc[j][9]  += xv * w2.y;
            acc[j][10] += xv * w2.z; acc[j][11] += xv * w2.w;
            acc[j][12] += xv * w3.x; acc[j][13] += xv * w3.y;
            acc[j][14] += xv * w3.z; acc[j][15] += xv * w3.w;
        }
    }
#pragma unroll
    for (int j = 0; j < 4; j++)
#pragma unroll
        for (int e = 0; e < E_NUM; e++) {
#pragma unroll
            for (int o = 16; o > 0; o >>= 1)
                acc[j][e] += __shfl_down_sync(0xFFFFFFFFu, acc[j][e], o);
        }

    if (lane == 0) {
#pragma unroll
        for (int j = 0; j < 4; j++) {
            int t = t0 + j;
            float v0 = -1e30f, v1 = -1e30f;
            int e0 = 0, e1 = 0;
#pragma unroll
            for (int e = 0; e < E_NUM; e++) {
                float val = acc[j][e] + gb[e];
                if (val > v0) { v1 = v0; e1 = e0; v0 = val; e0 = e; }
                else if (val > v1) { v1 = val; e1 = e; }
            }
            float ex = expf(v1 - v0);
            float s0 = 1.0f / (1.0f + ex);
            float s1 = ex * s0;
            g_tok_e[2 * t + 0] = e0; g_tok_s[2 * t + 0] = s0;
            g_tok_e[2 * t + 1] = e1; g_tok_s[2 * t + 1] = s1;
            atomicAdd(&g_cnt[e0], 1);
            atomicAdd(&g_cnt[e1], 1);
        }
    }
}

// ---------------- offsets ----------------
__global__ void offsets_kernel() {
    if (threadIdx.x == 0 && blockIdx.x == 0) {
        int o = 0;
        for (int e = 0; e < E_NUM; e++) {
            g_off[e] = o;
            o += ((g_cnt[e] + BM - 1) / BM) * BM;
        }
        g_off[E_NUM] = o;
    }
}

// ---------------- scatter ----------------
__global__ __launch_bounds__(256) void scatter_kernel() {
    int t = blockIdx.x * blockDim.x + threadIdx.x;
    if (t >= T_TOK) return;
#pragma unroll
    for (int k = 0; k < K_TOP; k++) {
        int e = g_tok_e[2 * t + k];
        int r = g_off[e] + atomicAdd(&g_cnt2[e], 1);
        g_row_token[r] = t;
        g_row_scale[r] = g_tok_s[2 * t + k];
        g_tok_row[2 * t + k] = r;
    }
}

// =========================================================================
// Grouped FP16 GEMMs (fp32 accumulate), 4-stage cp.async, B k-major in SMEM
// with ldmatrix.trans fragments. 128 threads = 4 warps (2x2), warp 64x64,
// 2 CTAs/SM.
// =========================================================================
template<int MODE>
__global__ __launch_bounds__(128, 2) void moe_gemm_kernel() {
    constexpr int KT   = (MODE == 0) ? D_DIM : FF_DIM;
    constexpr int NTOT = (MODE == 0) ? FF_DIM : D_DIM;
    constexpr int T    = KT / BK;

    int r0 = blockIdx.y * BM;
    int n0 = blockIdx.x * BN;
    if (g_row_token[r0] < 0) return;

    int e = 0;
    while (r0 >= g_off[e + 1]) e++;
    const __half* Bg = ((MODE == 0) ? g_wih : g_woh) + (size_t)e * D_DIM * FF_DIM;

    extern __shared__ __half smh[];
    __half* As = smh;
    __half* Bs = smh + NSTAGE * AS_STAGE;

    __shared__ int s_tok[BM];

    int tid  = threadIdx.x;
    int wid  = tid >> 5, lane = tid & 31;
    int wm   = wid & 1,  wn   = wid >> 1;
    int gid  = lane >> 2, tg  = lane & 3;

    if (MODE == 0) {
        int tk = g_row_token[r0 + tid];
        s_tok[tid] = tk < 0 ? 0 : tk;
    }
    __syncthreads();

    uint32_t aoff[4], boff[4];
    {
        int l = lane;
        int arow_in = l & 15;
        int akbyte  = (l >> 4) * 16;
#pragma unroll
        for (int mt = 0; mt < 4; mt++)
            aoff[mt] = (uint32_t)((wm * 64 + mt * 16 + arow_in) * AS_STRIDE * 2 + akbyte);
        int i4 = l >> 3, j = l & 7;
        int krow = (i4 & 1) * 8 + j;
        int nadd = (i4 >> 1) * 8;
#pragma unroll
        for (int q = 0; q < 4; q++)
            boff[q] = (uint32_t)((krow * BS_STRIDE + wn * 64 + q * 16 + nadd) * 2);
    }
    uint32_t aBase = su32(As), bBase = su32(Bs);

    auto load_stage = [&](int kt, int s) {
        int k0 = kt * BK;
#pragma unroll
        for (int j = 0; j < 4; j++) {
            int c = tid + 128 * j;
            int row = c >> 2;
            int seg = (c & 3) * 8;
            const __half* src;
            if (MODE == 0) src = g_xnr + (size_t)s_tok[row] * D_DIM + k0 + seg;
            else           src = g_h   + (size_t)(r0 + row) * FF_DIM + k0 + seg;
            cp16(&As[s * AS_STAGE + row * AS_STRIDE + seg], src);
        }
#pragma unroll
        for (int j = 0; j < 4; j++) {
            int c = tid + 128 * j;
            int row = c >> 4;
            int seg = (c & 15) * 8;
            const __half* src = Bg + (size_t)(k0 + row) * NTOT + n0 + seg;
            cp16(&Bs[s * BS_STAGE + row * BS_STRIDE + seg], src);
        }
        cp_commit();
    };

    float c[4][8][4];
#pragma unroll
    for (int mt = 0; mt < 4; mt++)
#pragma unroll
        for (int nt = 0; nt < 8; nt++)
#pragma unroll
            for (int i = 0; i < 4; i++) c[mt][nt][i] = 0.0f;

    load_stage(0, 0);
    load_stage(1, 1);
    load_stage(2, 2);

    int s = 0;
    for (int i = 0; i < T; i++) {
        if (i + 3 < T)      asm volatile("cp.async.wait_group 2;" ::: "memory");
        else if (i + 2 < T) asm volatile("cp.async.wait_group 1;" ::: "memory");
        else                asm volatile("cp.async.wait_group 0;" ::: "memory");
        __syncthreads();    // stage s ready; stage (s+3)%NSTAGE free

        if (i + 3 < T) load_stage(i + 3, (s + 3) % NSTAGE);

        uint32_t stA = aBase + (uint32_t)(s * AS_STAGE * 2);
        uint32_t stB = bBase + (uint32_t)(s * BS_STAGE * 2);
#pragma unroll
        for (int kk = 0; kk < BK; kk += 16) {
            unsigned a[4][4], b[4][4];
#pragma unroll
            for (int mt = 0; mt < 4; mt++)
                ldsm_x4(a[mt], stA + aoff[mt] + kk * 2);
#pragma unroll
            for (int q = 0; q < 4; q++)
                ldsm_x4_trans(b[q], stB + boff[q] + kk * BS_STRIDE * 2);
#pragma unroll
            for (int mt = 0; mt < 4; mt++)
#pragma unroll
                for (int q = 0; q < 4; q++) {
                    mma_f16(c[mt][2 * q + 0], a[mt], &b[q][0]);
                    mma_f16(c[mt][2 * q + 1], a[mt], &b[q][2]);
                }
        }
        s = (s + 1) % NSTAGE;
    }

#pragma unroll
    for (int mt = 0; mt < 4; mt++) {
        int rA = r0 + wm * 64 + mt * 16 + gid;
        if (MODE == 0) {
#pragma unroll
            for (int nt = 0; nt < 8; nt++) {
                int col = n0 + wn * 64 + (nt >> 1) * 16 + (nt & 1) * 8 + tg * 2;
                *(__half2*)&g_h[(size_t)rA * FF_DIM + col] =
                    __floats2half2_rn(fmaxf(c[mt][nt][0], 0.f), fmaxf(c[mt][nt][1], 0.f));
                *(__half2*)&g_h[(size_t)(rA + 8) * FF_DIM + col] =
                    __floats2half2_rn(fmaxf(c[mt][nt][2], 0.f), fmaxf(c[mt][nt][3], 0.f));
            }
        } else {
            float s0 = g_row_scale[rA];
            float s1 = g_row_scale[rA + 8];
#pragma unroll
            for (int nt = 0; nt < 8; nt++) {
                int col = n0 + wn * 64 + (nt >> 1) * 16 + (nt & 1) * 8 + tg * 2;
                float2 lo, hi;
                lo.x = s0 * c[mt][nt][0]; lo.y = s0 * c[mt][nt][1];
                hi.x = s1 * c[mt][nt][2]; hi.y = s1 * c[mt][nt][3];
                *(float2*)&g_y[(size_t)rA       * D_DIM + col] = lo;
                *(float2*)&g_y[(size_t)(rA + 8) * D_DIM + col] = hi;
            }
        }
    }
}

// ---------------- combine ----------------
__global__ __launch_bounds__(256) void combine_kernel(const float* __restrict__ hidden,
                                                      float* __restrict__ out) {
    int i = blockIdx.x * blockDim.x + threadIdx.x;
    int t = i >> 8;
    int d4 = i & 255;
    int r0 = g_tok_row[2 * t + 0];
    int r1 = g_tok_row[2 * t + 1];
    float4 h  = ((const float4*)hidden)[i];
    float4 y0 = ((const float4*)(g_y + (size_t)r0 * D_DIM))[d4];
    float4 y1 = ((const float4*)(g_y + (size_t)r1 * D_DIM))[d4];
    float4 o;
    o.x = h.x + y0.x + y1.x;
    o.y = h.y + y0.y + y1.y;
    o.z = h.z + y0.z + y1.z;
    o.w = h.w + y0.w + y1.w;
    ((float4*)out)[i] = o;
}

// ---------------- launch ----------------
extern "C" void kernel_launch(void* const* d_in, const int* in_sizes, int n_in,
                              void* d_out, int out_size) {
    const float* hidden = (const float*)d_in[0];
    const float* ln_w   = (const float*)d_in[1];
    const float* gate_w = (const float*)d_in[2];
    const float* gate_b = (const float*)d_in[3];
    const float* wi     = (const float*)d_in[4];
    const float* wo     = (const float*)d_in[5];
    float* out = (float*)d_out;

    static cudaStream_t s2 = nullptr;
    static cudaEvent_t evFork = nullptr, evWi = nullptr, evWo = nullptr;
    static int configured = 0;
    if (!configured) {
        cudaFuncSetAttribute(moe_gemm_kernel<0>, cudaFuncAttributeMaxDynamicSharedMemorySize, SMEM_DYN);
        cudaFuncSetAttribute(moe_gemm_kernel<1>, cudaFuncAttributeMaxDynamicSharedMemorySize, SMEM_DYN);
        cudaStreamCreateWithFlags(&s2, cudaStreamNonBlocking);
        cudaEventCreateWithFlags(&evFork, cudaEventDisableTiming);
        cudaEventCreateWithFlags(&evWi, cudaEventDisableTiming);
        cudaEventCreateWithFlags(&evWo, cudaEventDisableTiming);
        configured = 1;
    }

    __half* wih; cudaGetSymbolAddress((void**)&wih, g_wih);
    __half* woh; cudaGetSymbolAddress((void**)&woh, g_woh);
    const unsigned WBLK = (unsigned)((size_t)E_NUM * D_DIM * FF_DIM / 4 / 256);

    // fork: converts on s2; wi first (GEMM1 dep), wo overlaps GEMM1
    cudaEventRecord(evFork, 0);
    cudaStreamWaitEvent(s2, evFork, 0);
    convert_kernel<<<WBLK, 256, 0, s2>>>(wi, wih);
    cudaEventRecord(evWi, s2);
    convert_kernel<<<WBLK, 256, 0, s2>>>(wo, woh);
    cudaEventRecord(evWo, s2);

    // token path
    rmsnorm_kernel<<<T_TOK, 256>>>(hidden, ln_w);          // resets scratch
    gate_kernel<<<T_TOK / 32, 256>>>(gate_w, gate_b);
    offsets_kernel<<<1, 32>>>();
    scatter_kernel<<<(T_TOK + 255) / 256, 256>>>();

    cudaStreamWaitEvent(0, evWi, 0);
    moe_gemm_kernel<0><<<dim3(FF_DIM / BN, ROWS_MAX / BM), 128, SMEM_DYN>>>();
    cudaStreamWaitEvent(0, evWo, 0);
    moe_gemm_kernel<1><<<dim3(D_DIM / BN, ROWS_MAX / BM), 128, SMEM_DYN>>>();
    combine_kernel<<<(T_TOK * D_DIM / 4) / 256, 256>>>(hidden, out);
}